// round 14
// baseline (speedup 1.0000x reference)
#include <cuda_runtime.h>
#include <cuda_bf16.h>
#include <math.h>
#include <stdint.h>

#define BB 256
#define TT 256
#define DD 128
#define HH 512
#define G3 1536
#define NTH 256
#define GCTAS 148
typedef unsigned u32;
typedef __nv_bfloat16 bf;

__device__ float g_h[BB*HH];
__device__ float g_hp[BB*HH];
__device__ float g_gh0[BB*G3];
__device__ bf g_h_hi[BB*HH],  g_h_lo[BB*HH];
__device__ bf g_hp_hi[BB*HH], g_hp_lo[BB*HH];
__device__ bf g_imp_hi[BB*DD], g_imp_lo[BB*DD];
__device__ unsigned g_gbar[2*32];
__device__ volatile unsigned g_grel[2*32];
__device__ bf wA_hi[1664*HH], wA_lo[1664*HH];  // [W_hh0 ; W_out]
__device__ bf wB_hi[G3*DD],   wB_lo[G3*DD];    // W_ih0 gate-blocked by 8
__device__ bf wC_hi[3072*HH], wC_lo[3072*HH];  // [i-gates(24)|h-gates(24)] per 8-j block

__device__ __forceinline__ void splitw(float x, bf* hi, bf* lo){
    bf h = __float2bfloat16(x);
    *hi = h; *lo = __float2bfloat16(x - __bfloat162float(h));
}

__global__ void init_kernel(const float* W_ih0, const float* W_hh0,
                            const float* W_ih1, const float* W_hh1,
                            const float* W_out){
    int idx = blockIdx.x*blockDim.x + threadIdx.x;
    int gs  = gridDim.x*blockDim.x;
    if (idx < 2*32){ g_gbar[idx] = 0u; g_grel[idx] = 0u; }
    for (int i = idx; i < BB*HH; i += gs){
        g_h[i] = 0.f; g_h_hi[i] = __float2bfloat16(0.f); g_h_lo[i] = __float2bfloat16(0.f);
    }
    for (int i = idx; i < 1664*HH; i += gs){
        int n = i/HH, k = i - n*HH;
        float x = (n < G3) ? W_hh0[(size_t)n*HH + k] : W_out[(size_t)(n-G3)*HH + k];
        splitw(x, &wA_hi[i], &wA_lo[i]);
    }
    for (int i = idx; i < G3*DD; i += gs){
        int q = i/DD, k = i - q*DD;
        int gi = q/24, w = q%24, gate = w>>3, j = gi*8 + (w&7);
        splitw(W_ih0[(size_t)(gate*HH + j)*DD + k], &wB_hi[i], &wB_lo[i]);
    }
    for (int i = idx; i < 3072*HH; i += gs){
        int q = i/HH, k = i - q*HH;
        int gi = q/48, w = q%48, half = w/24, g3 = (w%24)>>3, jo = w&7;
        int j = gi*8 + jo;
        float x = (half == 0) ? W_ih1[(size_t)(g3*HH + j)*HH + k]
                              : W_hh1[(size_t)(g3*HH + j)*HH + k];
        splitw(x, &wC_hi[i], &wC_lo[i]);
    }
}

__device__ __forceinline__ u32 s2u(const void* p){
    u32 a; asm("{ .reg .u64 t; cvta.to.shared.u64 t, %1; cvt.u32.u64 %0, t; }" : "=r"(a) : "l"(p));
    return a;
}
__device__ __forceinline__ void cpasync16(u32 dst, const void* src){
    asm volatile("cp.async.cg.shared.global [%0], [%1], 16;" :: "r"(dst), "l"(src));
}
#define CP_COMMIT() asm volatile("cp.async.commit_group;" ::: "memory")
#define CP_WAIT0()  asm volatile("cp.async.wait_group 0;" ::: "memory")

__device__ __forceinline__ void mma_bf(float* d, u32 a0,u32 a1,u32 a2,u32 a3, u32 b0,u32 b1){
    asm volatile("mma.sync.aligned.m16n8k16.row.col.f32.bf16.bf16.f32 "
        "{%0,%1,%2,%3},{%4,%5,%6,%7},{%8,%9},{%0,%1,%2,%3};"
        : "+f"(d[0]),"+f"(d[1]),"+f"(d[2]),"+f"(d[3])
        : "r"(a0),"r"(a1),"r"(a2),"r"(a3),"r"(b0),"r"(b1));
}
__device__ __forceinline__ void ldsm4(u32* r, u32 a){
    asm volatile("ldmatrix.sync.aligned.m8n8.x4.shared.b16 {%0,%1,%2,%3}, [%4];"
        : "=r"(r[0]),"=r"(r[1]),"=r"(r[2]),"=r"(r[3]) : "r"(a));
}
__device__ __forceinline__ void ldsm2(u32* r, u32 a){
    asm volatile("ldmatrix.sync.aligned.m8n8.x2.shared.b16 {%0,%1}, [%2];"
        : "=r"(r[0]),"=r"(r[1]) : "r"(a));
}

// Group-local barrier: only the group's 148 CTAs participate.
__device__ __forceinline__ void group_barrier(int grp, unsigned &p){
    __syncthreads();
    p += 1u;
    if (threadIdx.x == 0){
        __threadfence();
        unsigned old = atomicAdd(&g_gbar[grp*32], 1u);
        if (old == p*(unsigned)GCTAS - 1u){
            g_grel[grp*32] = p;
            __threadfence();
        } else {
            int sp = 0;
            while (g_grel[grp*32] < p) if (++sp > 256) __nanosleep(32);
        }
    }
    __syncthreads();
}
__device__ __forceinline__ float sigf(float x){ return 1.f/(1.f+expf(-x)); }

// ---- smem: 2-buffer ring (A 64 rows hi/lo + W 48 rows hi/lo) + resident B weights
#define AH_OFF  0u
#define AL_OFF  9216u
#define WH_OFF  18432u
#define WL_OFF  25344u
#define BUF_SZ  32256u
#define RESB_HI 64512u
#define RESB_LO 71424u
#define SMEMSZ  78336

extern __shared__ __align__(16) char smc[];

template<int WROWS>
__device__ __forceinline__ void load_chunk(int buf, const bf* Ahi, const bf* Alo, int lda,
                                           const bf* W1, const bf* W2, int KW, int kc)
{
    const int tid = threadIdx.x;
    const u32 b = s2u(smc) + (u32)buf*BUF_SZ;
    int seg = tid;
    #pragma unroll
    for (int i = 0; i < 2; i++, seg += NTH){
        int r = seg >> 3, c = seg & 7;
        u32 d = b + r*144 + c*16;
        cpasync16(d + AH_OFF, Ahi + (size_t)r*lda + kc + c*8);
        cpasync16(d + AL_OFF, Alo + (size_t)r*lda + kc + c*8);
    }
    if (WROWS > 0){
        for (int s = tid; s < WROWS*8; s += NTH){
            int r = s >> 3, c = s & 7;
            u32 d = b + r*144 + c*16;
            cpasync16(d + WH_OFF, W1 + (size_t)r*KW + kc + c*8);
            cpasync16(d + WL_OFF, W2 + (size_t)r*KW + kc + c*8);
        }
    }
}

template<int NFR>
__device__ __forceinline__ void mma_chunk(u32 sAh, u32 sAl, u32 sWh, u32 sWl,
                                          int wm, int wn, float (*accH)[4], float (*accM)[4])
{
    const int lane = threadIdx.x & 31;
    const int lg = lane & 7, grp = lane >> 3;
    const u32 arow = (u32)(wm + lg + (grp & 1)*8) * 144 + ((grp >> 1) & 1)*16;
    const int l16 = lane & 15;
    const u32 brow0 = (u32)(l16 & 7) * 144 + (u32)(l16 >> 3) * 16;
    #pragma unroll
    for (int k16 = 0; k16 < 4; k16++){
        u32 ah[4], al[4];
        ldsm4(ah, sAh + arow + k16*32);
        ldsm4(al, sAl + arow + k16*32);
        #pragma unroll
        for (int nf = 0; nf < NFR; nf++){
            u32 boff = brow0 + (u32)(wn + 8*nf)*144 + k16*32;
            u32 bh[2], bl[2];
            ldsm2(bh, sWh + boff);
            ldsm2(bl, sWl + boff);
            mma_bf(accH[nf], ah[0],ah[1],ah[2],ah[3], bh[0],bh[1]);
            mma_bf(accM[nf], ah[0],ah[1],ah[2],ah[3], bl[0],bl[1]);
            mma_bf(accM[nf], al[0],al[1],al[2],al[3], bh[0],bh[1]);
        }
    }
}

template<int NC, int WROWS, int NFR>
__device__ __forceinline__ void gemm_run(const bf* Ahi, const bf* Alo, int lda,
    const bf* W1, const bf* W2, int KW, int wm, int wn,
    float (*accH)[4], float (*accM)[4])
{
    #pragma unroll
    for (int n = 0; n < NFR; n++)
        #pragma unroll
        for (int q = 0; q < 4; q++){ accH[n][q] = 0.f; accM[n][q] = 0.f; }

    load_chunk<WROWS>(0, Ahi, Alo, lda, W1, W2, KW, 0);
    CP_COMMIT();
    const u32 sb = s2u(smc);
    for (int ch = 0; ch < NC; ch++){
        CP_WAIT0();
        __syncthreads();
        if (ch + 1 < NC){
            load_chunk<WROWS>((ch+1)&1, Ahi, Alo, lda, W1, W2, KW, (ch+1)*64);
            CP_COMMIT();
        }
        const u32 b = sb + (u32)(ch&1)*BUF_SZ;
        mma_chunk<NFR>(b+AH_OFF, b+AL_OFF, b+WH_OFF, b+WL_OFF, wm, wn, accH, accM);
    }
}

__global__ void __launch_bounds__(NTH, 2) brits_kernel(
    const float* __restrict__ X,     const float* __restrict__ Msk,
    const float* __restrict__ b_ih0, const float* __restrict__ b_hh0,
    const float* __restrict__ b_ih1, const float* __restrict__ b_hh1,
    const float* __restrict__ W_out, const float* __restrict__ b_out,
    float* __restrict__ out)
{
    const int tid = threadIdx.x, wid = tid >> 5, lane = tid & 31, bx = blockIdx.x;
    const int g = lane >> 2, t = lane & 3;
    const int half = wid & 1;
    const int wm = (wid >> 1) * 16;
    float* xbuf = (float*)smc;

    // batch-split group: CTAs [0,148) own rows [0,128); [148,296) own rows [128,256)
    const int grp  = (bx >= GCTAS) ? 1 : 0;
    const int lbx  = bx - grp*GCTAS;
    const int mb   = grp * 128;           // batch-row base for this group

    float* pre_o = out;
    float* out_o = out + (size_t)BB*TT*DD;
    float* hf_o  = out + (size_t)2*BB*TT*DD;
    float* hid_o = hf_o + (size_t)BB*HH;

    unsigned p = 0;
    const u32 sb = s2u(smc);

    for (int ts = 0; ts < TT; ts++){
        // ---- A: [gh0 | est]. 104 tiles 64m x 32n (m within group), K=512
        for (int tile = lbx; tile < 104; tile += GCTAS){
            const int m0 = mb + (tile / 52) * 64, n0 = (tile % 52) * 32;
            const int wn = half * 16;
            float accH[2][4], accM[2][4];
            gemm_run<8,32,2>(g_h_hi + (size_t)m0*HH, g_h_lo + (size_t)m0*HH, HH,
                             wA_hi + (size_t)n0*HH, wA_lo + (size_t)n0*HH, HH, wm, wn, accH, accM);
            #pragma unroll
            for (int nf = 0; nf < 2; nf++)
                #pragma unroll
                for (int rh = 0; rh < 2; rh++)
                    #pragma unroll
                    for (int d = 0; d < 2; d++){
                        int m = m0 + wm + g + 8*rh;
                        int n = n0 + wn + 8*nf + 2*t + d;
                        float v = accH[nf][rh*2+d] + accM[nf][rh*2+d];
                        if (n < G3) g_gh0[m*G3 + n] = v + b_hh0[n];
                        else {
                            int dd = n - G3;
                            float est = v + b_out[dd];
                            int io = (m*TT + ts)*DD + dd;
                            pre_o[io] = est;
                            float imp = est + Msk[io] * (X[io] - est);
                            bf hi = __float2bfloat16(imp);
                            g_imp_hi[m*DD + dd] = hi;
                            g_imp_lo[m*DD + dd] = __float2bfloat16(imp - __bfloat162float(hi));
                            if (ts > 0) out_o[io - DD] = imp;
                        }
                    }
        }
        group_barrier(grp, p);

        // ---- B: fused cell-0. 128 tiles 64m x 24n, K=128 split across halves. Resident W.
        for (int tile = lbx; tile < 128; tile += GCTAS){
            const int m0 = mb + (tile >> 6) * 64, jt = tile & 63, j0 = jt * 8;
            const int qB = jt * 24;
            for (int s = tid; s < 2*24*8; s += NTH){
                int ch = s / 192, r = (s >> 3) % 24, c = s & 7;
                *(uint4*)(smc + RESB_HI + (ch*24 + r)*144 + c*16) =
                    __ldg((const uint4*)(wB_hi + (size_t)(qB + r)*DD + ch*64 + c*8));
                *(uint4*)(smc + RESB_LO + (ch*24 + r)*144 + c*16) =
                    __ldg((const uint4*)(wB_lo + (size_t)(qB + r)*DD + ch*64 + c*8));
            }
            load_chunk<0>(0, g_imp_hi + (size_t)m0*DD, g_imp_lo + (size_t)m0*DD, DD,
                          (const bf*)0, (const bf*)0, DD, 0);
            load_chunk<0>(1, g_imp_hi + (size_t)m0*DD, g_imp_lo + (size_t)m0*DD, DD,
                          (const bf*)0, (const bf*)0, DD, 64);
            CP_COMMIT(); CP_WAIT0();
            __syncthreads();
            float accH[3][4], accM[3][4];
            #pragma unroll
            for (int n = 0; n < 3; n++)
                #pragma unroll
                for (int q = 0; q < 4; q++){ accH[n][q] = 0.f; accM[n][q] = 0.f; }
            const u32 b = sb + (u32)half*BUF_SZ;
            mma_chunk<3>(b+AH_OFF, b+AL_OFF,
                         sb + RESB_HI + (u32)half*24*144, sb + RESB_LO + (u32)half*24*144,
                         wm, 0, accH, accM);
            __syncthreads();
            if (half == 1)
                #pragma unroll
                for (int nf = 0; nf < 3; nf++)
                    #pragma unroll
                    for (int rh = 0; rh < 2; rh++)
                        #pragma unroll
                        for (int d = 0; d < 2; d++)
                            xbuf[(wm + g + 8*rh)*24 + nf*8 + 2*t + d] =
                                accH[nf][rh*2+d] + accM[nf][rh*2+d];
            __syncthreads();
            if (half == 0)
                #pragma unroll
                for (int rh = 0; rh < 2; rh++)
                    #pragma unroll
                    for (int d = 0; d < 2; d++){
                        int m = m0 + wm + g + 8*rh;
                        int j = j0 + 2*t + d;
                        int q = rh*2 + d;
                        int xb = (wm + g + 8*rh)*24 + 2*t + d;
                        float gr = accH[0][q]+accM[0][q] + xbuf[xb]    + b_ih0[j]      + __ldcg(&g_gh0[m*G3 + j]);
                        float gz = accH[1][q]+accM[1][q] + xbuf[xb+8]  + b_ih0[HH + j] + __ldcg(&g_gh0[m*G3 + HH + j]);
                        float gn = accH[2][q]+accM[2][q] + xbuf[xb+16] + b_ih0[2*HH + j];
                        float hn = __ldcg(&g_gh0[m*G3 + 2*HH + j]);
                        float r = sigf(gr), z = sigf(gz);
                        float nn = tanhf(gn + r * hn);
                        float hp = (1.f - z) * nn + z * __ldcg(&g_h[m*HH + j]);
                        g_hp[m*HH + j] = hp;
                        bf hi = __float2bfloat16(hp);
                        g_hp_hi[m*HH + j] = hi;
                        g_hp_lo[m*HH + j] = __float2bfloat16(hp - __bfloat162float(hi));
                    }
            __syncthreads();
        }
        group_barrier(grp, p);

        // ---- C: fused cell-1. 128 tiles 64m x 48n (half0 i-gates, half1 h-gates), K=512
        for (int tile = lbx; tile < 128; tile += GCTAS){
            const int m0 = mb + (tile >> 6) * 64, nt = tile & 63;
            const int q0 = nt * 48, j0 = nt * 8;
            const int wn = half * 24;
            float accH[3][4], accM[3][4];
            gemm_run<8,48,3>(g_hp_hi + (size_t)m0*HH, g_hp_lo + (size_t)m0*HH, HH,
                             wC_hi + (size_t)q0*HH, wC_lo + (size_t)q0*HH, HH, wm, wn, accH, accM);
            if (half == 1)
                #pragma unroll
                for (int nf = 0; nf < 3; nf++)
                    #pragma unroll
                    for (int rh = 0; rh < 2; rh++)
                        #pragma unroll
                        for (int d = 0; d < 2; d++)
                            xbuf[((wm + g + 8*rh)*8 + 2*t + d)*3 + nf] =
                                accH[nf][rh*2+d] + accM[nf][rh*2+d];
            __syncthreads();
            if (half == 0)
                #pragma unroll
                for (int rh = 0; rh < 2; rh++)
                    #pragma unroll
                    for (int d = 0; d < 2; d++){
                        int ml = wm + g + 8*rh, m = m0 + ml;
                        int jo = 2*t + d, j = j0 + jo;
                        int q = rh*2 + d;
                        const float* xb = &xbuf[(ml*8 + jo)*3];
                        float ir = accH[0][q]+accM[0][q], iz = accH[1][q]+accM[1][q], in_ = accH[2][q]+accM[2][q];
                        float hr = xb[0], hz = xb[1], hn = xb[2];
                        float r = sigf(ir + b_ih1[j] + hr + b_hh1[j]);
                        float z = sigf(iz + b_ih1[HH+j] + hz + b_hh1[HH+j]);
                        float nn = tanhf(in_ + b_ih1[2*HH+j] + r * (hn + b_hh1[2*HH+j]));
                        float hnew = (1.f - z) * nn + z * __ldcg(&g_hp[m*HH + j]);
                        g_h[m*HH + j] = hnew;
                        bf hi = __float2bfloat16(hnew);
                        g_h_hi[m*HH + j] = hi;
                        g_h_lo[m*HH + j] = __float2bfloat16(hnew - __bfloat162float(hi));
                        hid_o[((size_t)m*TT + ts)*HH + j] = hnew;
                    }
            __syncthreads();
        }
        group_barrier(grp, p);
    }

    // tail: per-group partition of the group's 128 batch rows
    for (int idx = lbx*NTH + tid; idx < 128*DD; idx += GCTAS*NTH){
        int b = mb + (idx >> 7), d = idx & 127;
        const float4* hv = (const float4*)(g_h + (size_t)b*HH);
        const float4* wv = (const float4*)(W_out + (size_t)d*HH);
        float s = b_out[d];
        #pragma unroll 8
        for (int q = 0; q < HH/4; q++){
            float4 a = __ldcg(&hv[q]); float4 w = __ldg(&wv[q]);
            s += a.x*w.x + a.y*w.y + a.z*w.z + a.w*w.w;
        }
        out_o[((size_t)b*TT + (TT-1))*DD + d] = s;
    }
    for (int idx = lbx*NTH + tid; idx < 128*HH; idx += GCTAS*NTH){
        int b = mb + (idx >> 9), j = idx & 511;
        hf_o[(size_t)b*HH + j] = __ldcg(&g_h[(size_t)b*HH + j]);
    }
}

extern "C" void kernel_launch(void* const* d_in, const int* in_sizes, int n_in,
                              void* d_out, int out_size) {
    const float* X     = (const float*)d_in[0];
    const float* Msk   = (const float*)d_in[1];
    const float* W_ih0 = (const float*)d_in[2];
    const float* W_hh0 = (const float*)d_in[3];
    const float* b_ih0 = (const float*)d_in[4];
    const float* b_hh0 = (const float*)d_in[5];
    const float* W_ih1 = (const float*)d_in[6];
    const float* W_hh1 = (const float*)d_in[7];
    const float* b_ih1 = (const float*)d_in[8];
    const float* b_hh1 = (const float*)d_in[9];
    const float* W_out = (const float*)d_in[10];
    const float* b_out = (const float*)d_in[11];

    static bool done = false;
    if (!done){
        cudaFuncSetAttribute(brits_kernel, cudaFuncAttributeMaxDynamicSharedMemorySize, SMEMSZ);
        done = true;
    }
    init_kernel<<<512, 256>>>(W_ih0, W_hh0, W_ih1, W_hh1, W_out);
    brits_kernel<<<2*GCTAS, NTH, SMEMSZ>>>(X, Msk, b_ih0, b_hh0, b_ih1, b_hh1,
                                           W_out, b_out, (float*)d_out);
}

// round 15
// speedup vs baseline: 1.4814x; 1.4814x over previous
#include <cuda_runtime.h>
#include <cuda_bf16.h>
#include <math.h>
#include <stdint.h>

#define BB 256
#define TT 256
#define DD 128
#define HH 512
#define G3 1536
#define NTH 256
typedef unsigned u32;
typedef __nv_bfloat16 bf;

__device__ float g_h[BB*HH];
__device__ float g_hp[BB*HH];
__device__ float g_gh0[BB*G3];
__device__ bf g_h_hi[BB*HH],  g_h_lo[BB*HH];
__device__ bf g_hp_hi[BB*HH], g_hp_lo[BB*HH];
__device__ bf g_imp_hi[BB*DD], g_imp_lo[BB*DD];
__device__ unsigned g_bar;
__device__ volatile unsigned g_rel;
__device__ bf wA_hi[1664*HH], wA_lo[1664*HH];  // [W_hh0 ; W_out]
__device__ bf wB_hi[G3*DD],   wB_lo[G3*DD];    // W_ih0 gate-blocked by 8
__device__ bf wC_hi[2048*HH], wC_lo[2048*HH];  // per 8-j block: [rc(8),zc(8),in(8),hn(8)]

__device__ __forceinline__ void splitw(float x, bf* hi, bf* lo){
    bf h = __float2bfloat16(x);
    *hi = h; *lo = __float2bfloat16(x - __bfloat162float(h));
}

__global__ void init_kernel(const float* W_ih0, const float* W_hh0,
                            const float* W_ih1, const float* W_hh1,
                            const float* W_out){
    int idx = blockIdx.x*blockDim.x + threadIdx.x;
    int gs  = gridDim.x*blockDim.x;
    if (idx == 0){ g_bar = 0u; g_rel = 0u; }
    for (int i = idx; i < BB*HH; i += gs){
        g_h[i] = 0.f; g_h_hi[i] = __float2bfloat16(0.f); g_h_lo[i] = __float2bfloat16(0.f);
    }
    for (int i = idx; i < 1664*HH; i += gs){
        int n = i/HH, k = i - n*HH;
        float x = (n < G3) ? W_hh0[(size_t)n*HH + k] : W_out[(size_t)(n-G3)*HH + k];
        splitw(x, &wA_hi[i], &wA_lo[i]);
    }
    for (int i = idx; i < G3*DD; i += gs){
        int q = i/DD, k = i - q*DD;
        int gi = q/24, w = q%24, gate = w>>3, j = gi*8 + (w&7);
        splitw(W_ih0[(size_t)(gate*HH + j)*DD + k], &wB_hi[i], &wB_lo[i]);
    }
    // cell-1 input == hidden -> combine r,z weights: rc = W_ih1_r + W_hh1_r, zc likewise.
    for (int i = idx; i < 2048*HH; i += gs){
        int q = i/HH, k = i - q*HH;
        int blk = q/32, w = q%32, gate = w>>3, jo = w&7;
        int j = blk*8 + jo;
        float x;
        if (gate == 0)      x = W_ih1[(size_t)j*HH + k]          + W_hh1[(size_t)j*HH + k];
        else if (gate == 1) x = W_ih1[(size_t)(HH + j)*HH + k]   + W_hh1[(size_t)(HH + j)*HH + k];
        else if (gate == 2) x = W_ih1[(size_t)(2*HH + j)*HH + k];
        else                x = W_hh1[(size_t)(2*HH + j)*HH + k];
        splitw(x, &wC_hi[i], &wC_lo[i]);
    }
}

__device__ __forceinline__ u32 s2u(const void* p){
    u32 a; asm("{ .reg .u64 t; cvta.to.shared.u64 t, %1; cvt.u32.u64 %0, t; }" : "=r"(a) : "l"(p));
    return a;
}
__device__ __forceinline__ void cpasync16(u32 dst, const void* src){
    asm volatile("cp.async.cg.shared.global [%0], [%1], 16;" :: "r"(dst), "l"(src));
}
#define CP_COMMIT() asm volatile("cp.async.commit_group;" ::: "memory")
#define CP_WAIT0()  asm volatile("cp.async.wait_group 0;" ::: "memory")

__device__ __forceinline__ void mma_bf(float* d, u32 a0,u32 a1,u32 a2,u32 a3, u32 b0,u32 b1){
    asm volatile("mma.sync.aligned.m16n8k16.row.col.f32.bf16.bf16.f32 "
        "{%0,%1,%2,%3},{%4,%5,%6,%7},{%8,%9},{%0,%1,%2,%3};"
        : "+f"(d[0]),"+f"(d[1]),"+f"(d[2]),"+f"(d[3])
        : "r"(a0),"r"(a1),"r"(a2),"r"(a3),"r"(b0),"r"(b1));
}
__device__ __forceinline__ void ldsm4(u32* r, u32 a){
    asm volatile("ldmatrix.sync.aligned.m8n8.x4.shared.b16 {%0,%1,%2,%3}, [%4];"
        : "=r"(r[0]),"=r"(r[1]),"=r"(r[2]),"=r"(r[3]) : "r"(a));
}
__device__ __forceinline__ void ldsm2(u32* r, u32 a){
    asm volatile("ldmatrix.sync.aligned.m8n8.x2.shared.b16 {%0,%1}, [%2];"
        : "=r"(r[0]),"=r"(r[1]) : "r"(a));
}

__device__ __forceinline__ void grid_barrier(unsigned &target){
    __syncthreads();
    target += gridDim.x;
    if (threadIdx.x == 0){
        __threadfence();
        unsigned old = atomicAdd(&g_bar, 1u);
        if (old == target - 1u){
            g_rel = target;
            __threadfence();
        } else {
            int sp = 0;
            while (g_rel < target) if (++sp > 512) __nanosleep(64);
        }
    }
    __syncthreads();
}
__device__ __forceinline__ float sigf(float x){ return 1.f/(1.f+expf(-x)); }

// ---- smem: 2-buffer ring (A 64 rows hi/lo + W 48 rows hi/lo) + resident B weights
#define AH_OFF  0u
#define AL_OFF  9216u
#define WH_OFF  18432u
#define WL_OFF  25344u
#define BUF_SZ  32256u
#define RESB_HI 64512u
#define RESB_LO 71424u
#define SMEMSZ  78336

extern __shared__ __align__(16) char smc[];

template<int WROWS>
__device__ __forceinline__ void load_chunk(int buf, const bf* Ahi, const bf* Alo, int lda,
                                           const bf* W1, const bf* W2, int KW, int kc)
{
    const int tid = threadIdx.x;
    const u32 b = s2u(smc) + (u32)buf*BUF_SZ;
    int seg = tid;
    #pragma unroll
    for (int i = 0; i < 2; i++, seg += NTH){
        int r = seg >> 3, c = seg & 7;
        u32 d = b + r*144 + c*16;
        cpasync16(d + AH_OFF, Ahi + (size_t)r*lda + kc + c*8);
        cpasync16(d + AL_OFF, Alo + (size_t)r*lda + kc + c*8);
    }
    if (WROWS > 0){
        for (int s = tid; s < WROWS*8; s += NTH){
            int r = s >> 3, c = s & 7;
            u32 d = b + r*144 + c*16;
            cpasync16(d + WH_OFF, W1 + (size_t)r*KW + kc + c*8);
            cpasync16(d + WL_OFF, W2 + (size_t)r*KW + kc + c*8);
        }
    }
}

// 3 independent accumulator chains per n-fragment: H=Ah*Bh, M1=Ah*Bl, M2=Al*Bh
template<int NFR>
__device__ __forceinline__ void mma_chunk(u32 sAh, u32 sAl, u32 sWh, u32 sWl,
                                          int wm, int wn,
                                          float (*accH)[4], float (*accM1)[4], float (*accM2)[4])
{
    const int lane = threadIdx.x & 31;
    const int lg = lane & 7, grp = lane >> 3;
    const u32 arow = (u32)(wm + lg + (grp & 1)*8) * 144 + ((grp >> 1) & 1)*16;
    const int l16 = lane & 15;
    const u32 brow0 = (u32)(l16 & 7) * 144 + (u32)(l16 >> 3) * 16;
    #pragma unroll
    for (int k16 = 0; k16 < 4; k16++){
        u32 ah[4], al[4];
        ldsm4(ah, sAh + arow + k16*32);
        ldsm4(al, sAl + arow + k16*32);
        #pragma unroll
        for (int nf = 0; nf < NFR; nf++){
            u32 boff = brow0 + (u32)(wn + 8*nf)*144 + k16*32;
            u32 bh[2], bl[2];
            ldsm2(bh, sWh + boff);
            ldsm2(bl, sWl + boff);
            mma_bf(accH[nf],  ah[0],ah[1],ah[2],ah[3], bh[0],bh[1]);
            mma_bf(accM1[nf], ah[0],ah[1],ah[2],ah[3], bl[0],bl[1]);
            mma_bf(accM2[nf], al[0],al[1],al[2],al[3], bh[0],bh[1]);
        }
    }
}

template<int NC, int WROWS, int NFR>
__device__ __forceinline__ void gemm_run(const bf* Ahi, const bf* Alo, int lda,
    const bf* W1, const bf* W2, int KW, int wm, int wn,
    float (*accH)[4], float (*accM1)[4], float (*accM2)[4])
{
    #pragma unroll
    for (int n = 0; n < NFR; n++)
        #pragma unroll
        for (int q = 0; q < 4; q++){ accH[n][q] = 0.f; accM1[n][q] = 0.f; accM2[n][q] = 0.f; }

    load_chunk<WROWS>(0, Ahi, Alo, lda, W1, W2, KW, 0);
    CP_COMMIT();
    const u32 sb = s2u(smc);
    for (int ch = 0; ch < NC; ch++){
        CP_WAIT0();
        __syncthreads();
        if (ch + 1 < NC){
            load_chunk<WROWS>((ch+1)&1, Ahi, Alo, lda, W1, W2, KW, (ch+1)*64);
            CP_COMMIT();
        }
        const u32 b = sb + (u32)(ch&1)*BUF_SZ;
        mma_chunk<NFR>(b+AH_OFF, b+AL_OFF, b+WH_OFF, b+WL_OFF, wm, wn, accH, accM1, accM2);
    }
}

__global__ void __launch_bounds__(NTH, 2) brits_kernel(
    const float* __restrict__ X,     const float* __restrict__ Msk,
    const float* __restrict__ b_ih0, const float* __restrict__ b_hh0,
    const float* __restrict__ b_ih1, const float* __restrict__ b_hh1,
    const float* __restrict__ W_out, const float* __restrict__ b_out,
    float* __restrict__ out)
{
    const int tid = threadIdx.x, wid = tid >> 5, lane = tid & 31, bx = blockIdx.x;
    const int g = lane >> 2, t = lane & 3;
    const int half = wid & 1;
    const int wm = (wid >> 1) * 16;
    float* xbuf = (float*)smc;            // aliases ring buf0 (dead at epilogue)

    float* pre_o = out;
    float* out_o = out + (size_t)BB*TT*DD;
    float* hf_o  = out + (size_t)2*BB*TT*DD;
    float* hid_o = hf_o + (size_t)BB*HH;

    unsigned target = 0;
    const int gs   = gridDim.x * blockDim.x;
    const int gtid = bx * blockDim.x + tid;
    const u32 sb = s2u(smc);

    for (int ts = 0; ts < TT; ts++){
        // ---- A: [gh0 | est] = h @ [W_hh0;W_out]^T. 208 tiles 64m x 32n, K=512
        for (int tile = bx; tile < 208; tile += gridDim.x){
            const int m0 = (tile / 52) * 64, n0 = (tile % 52) * 32;
            const int wn = half * 16;
            float accH[2][4], accM1[2][4], accM2[2][4];
            gemm_run<8,32,2>(g_h_hi + (size_t)m0*HH, g_h_lo + (size_t)m0*HH, HH,
                             wA_hi + (size_t)n0*HH, wA_lo + (size_t)n0*HH, HH,
                             wm, wn, accH, accM1, accM2);
            #pragma unroll
            for (int nf = 0; nf < 2; nf++)
                #pragma unroll
                for (int rh = 0; rh < 2; rh++)
                    #pragma unroll
                    for (int d = 0; d < 2; d++){
                        int m = m0 + wm + g + 8*rh;
                        int n = n0 + wn + 8*nf + 2*t + d;
                        int q = rh*2 + d;
                        float v = accH[nf][q] + accM1[nf][q] + accM2[nf][q];
                        if (n < G3) g_gh0[m*G3 + n] = v + b_hh0[n];
                        else {
                            int dd = n - G3;
                            float est = v + b_out[dd];
                            int io = (m*TT + ts)*DD + dd;
                            pre_o[io] = est;
                            float imp = est + Msk[io] * (X[io] - est);
                            bf hi = __float2bfloat16(imp);
                            g_imp_hi[m*DD + dd] = hi;
                            g_imp_lo[m*DD + dd] = __float2bfloat16(imp - __bfloat162float(hi));
                            if (ts > 0) out_o[io - DD] = imp;
                        }
                    }
        }
        grid_barrier(target);

        // ---- B: fused cell-0. 256 tiles 64m x 24n, K=128 split across halves. Resident W.
        for (int tile = bx; tile < 256; tile += gridDim.x){
            const int m0 = (tile / 64) * 64, jt = tile % 64, j0 = jt * 8;
            const int qB = jt * 24;
            for (int s = tid; s < 2*24*8; s += NTH){
                int ch = s / 192, r = (s >> 3) % 24, c = s & 7;
                *(uint4*)(smc + RESB_HI + (ch*24 + r)*144 + c*16) =
                    __ldg((const uint4*)(wB_hi + (size_t)(qB + r)*DD + ch*64 + c*8));
                *(uint4*)(smc + RESB_LO + (ch*24 + r)*144 + c*16) =
                    __ldg((const uint4*)(wB_lo + (size_t)(qB + r)*DD + ch*64 + c*8));
            }
            load_chunk<0>(0, g_imp_hi + (size_t)m0*DD, g_imp_lo + (size_t)m0*DD, DD,
                          (const bf*)0, (const bf*)0, DD, 0);
            load_chunk<0>(1, g_imp_hi + (size_t)m0*DD, g_imp_lo + (size_t)m0*DD, DD,
                          (const bf*)0, (const bf*)0, DD, 64);
            CP_COMMIT(); CP_WAIT0();
            __syncthreads();
            float accH[3][4], accM1[3][4], accM2[3][4];
            #pragma unroll
            for (int n = 0; n < 3; n++)
                #pragma unroll
                for (int q = 0; q < 4; q++){ accH[n][q]=0.f; accM1[n][q]=0.f; accM2[n][q]=0.f; }
            const u32 b = sb + (u32)half*BUF_SZ;
            mma_chunk<3>(b+AH_OFF, b+AL_OFF,
                         sb + RESB_HI + (u32)half*24*144, sb + RESB_LO + (u32)half*24*144,
                         wm, 0, accH, accM1, accM2);
            __syncthreads();
            if (half == 1)
                #pragma unroll
                for (int nf = 0; nf < 3; nf++)
                    #pragma unroll
                    for (int rh = 0; rh < 2; rh++)
                        #pragma unroll
                        for (int d = 0; d < 2; d++){
                            int q = rh*2 + d;
                            xbuf[(wm + g + 8*rh)*24 + nf*8 + 2*t + d] =
                                accH[nf][q] + accM1[nf][q] + accM2[nf][q];
                        }
            __syncthreads();
            if (half == 0)
                #pragma unroll
                for (int rh = 0; rh < 2; rh++)
                    #pragma unroll
                    for (int d = 0; d < 2; d++){
                        int m = m0 + wm + g + 8*rh;
                        int j = j0 + 2*t + d;
                        int q = rh*2 + d;
                        int xb = (wm + g + 8*rh)*24 + 2*t + d;
                        float gr = accH[0][q]+accM1[0][q]+accM2[0][q] + xbuf[xb]    + b_ih0[j]      + __ldcg(&g_gh0[m*G3 + j]);
                        float gz = accH[1][q]+accM1[1][q]+accM2[1][q] + xbuf[xb+8]  + b_ih0[HH + j] + __ldcg(&g_gh0[m*G3 + HH + j]);
                        float gn = accH[2][q]+accM1[2][q]+accM2[2][q] + xbuf[xb+16] + b_ih0[2*HH + j];
                        float hn = __ldcg(&g_gh0[m*G3 + 2*HH + j]);
                        float r = sigf(gr), z = sigf(gz);
                        float nn = tanhf(gn + r * hn);
                        float hp = (1.f - z) * nn + z * __ldcg(&g_h[m*HH + j]);
                        g_hp[m*HH + j] = hp;
                        bf hi = __float2bfloat16(hp);
                        g_hp_hi[m*HH + j] = hi;
                        g_hp_lo[m*HH + j] = __float2bfloat16(hp - __bfloat162float(hi));
                    }
            __syncthreads();
        }
        grid_barrier(target);

        // ---- C: fused cell-1 (combined r/z weights). 256 tiles 64m x 32n, K=512.
        //      rows per 8-j block: [rc(8), zc(8) | in(8), hn(8)]; halves split 16/16.
        for (int tile = bx; tile < 256; tile += gridDim.x){
            const int m0 = (tile >> 6) * 64, jblk = tile & 63;
            const int j0 = jblk * 8, q0 = jblk * 32;
            const int wn = half * 16;
            float accH[2][4], accM1[2][4], accM2[2][4];
            gemm_run<8,32,2>(g_hp_hi + (size_t)m0*HH, g_hp_lo + (size_t)m0*HH, HH,
                             wC_hi + (size_t)q0*HH, wC_lo + (size_t)q0*HH, HH,
                             wm, wn, accH, accM1, accM2);
            if (half == 1)   // rows 16..31: in (nf=0), hn (nf=1)
                #pragma unroll
                for (int rh = 0; rh < 2; rh++)
                    #pragma unroll
                    for (int d = 0; d < 2; d++){
                        int ml = wm + g + 8*rh, jo = 2*t + d, q = rh*2 + d;
                        float* xp = &xbuf[(ml*8 + jo)*2];
                        xp[0] = accH[0][q] + accM1[0][q] + accM2[0][q];   // in
                        xp[1] = accH[1][q] + accM1[1][q] + accM2[1][q];   // hn
                    }
            __syncthreads();
            if (half == 0)   // rows 0..15: rc (nf=0), zc (nf=1)
                #pragma unroll
                for (int rh = 0; rh < 2; rh++)
                    #pragma unroll
                    for (int d = 0; d < 2; d++){
                        int ml = wm + g + 8*rh, m = m0 + ml;
                        int jo = 2*t + d, j = j0 + jo;
                        int q = rh*2 + d;
                        const float* xp = &xbuf[(ml*8 + jo)*2];
                        float rcv = accH[0][q] + accM1[0][q] + accM2[0][q];
                        float zcv = accH[1][q] + accM1[1][q] + accM2[1][q];
                        float r = sigf(rcv + b_ih1[j] + b_hh1[j]);
                        float z = sigf(zcv + b_ih1[HH + j] + b_hh1[HH + j]);
                        float nn = tanhf(xp[0] + b_ih1[2*HH + j] + r * (xp[1] + b_hh1[2*HH + j]));
                        float hnew = (1.f - z) * nn + z * __ldcg(&g_hp[m*HH + j]);
                        g_h[m*HH + j] = hnew;
                        bf hi = __float2bfloat16(hnew);
                        g_h_hi[m*HH + j] = hi;
                        g_h_lo[m*HH + j] = __float2bfloat16(hnew - __bfloat162float(hi));
                        hid_o[((size_t)m*TT + ts)*HH + j] = hnew;
                    }
            __syncthreads();
        }
        grid_barrier(target);
    }

    // tail
    for (int idx = gtid; idx < BB*DD; idx += gs){
        int b = idx >> 7, d = idx & 127;
        const float4* hv = (const float4*)(g_h + (size_t)b*HH);
        const float4* wv = (const float4*)(W_out + (size_t)d*HH);
        float s = b_out[d];
        #pragma unroll 8
        for (int q = 0; q < HH/4; q++){
            float4 a = __ldcg(&hv[q]); float4 w = __ldg(&wv[q]);
            s += a.x*w.x + a.y*w.y + a.z*w.z + a.w*w.w;
        }
        out_o[((size_t)b*TT + (TT-1))*DD + d] = s;
    }
    for (int idx = gtid; idx < BB*HH; idx += gs)
        hf_o[idx] = __ldcg(&g_h[idx]);
}

extern "C" void kernel_launch(void* const* d_in, const int* in_sizes, int n_in,
                              void* d_out, int out_size) {
    const float* X     = (const float*)d_in[0];
    const float* Msk   = (const float*)d_in[1];
    const float* W_ih0 = (const float*)d_in[2];
    const float* W_hh0 = (const float*)d_in[3];
    const float* b_ih0 = (const float*)d_in[4];
    const float* b_hh0 = (const float*)d_in[5];
    const float* W_ih1 = (const float*)d_in[6];
    const float* W_hh1 = (const float*)d_in[7];
    const float* b_ih1 = (const float*)d_in[8];
    const float* b_hh1 = (const float*)d_in[9];
    const float* W_out = (const float*)d_in[10];
    const float* b_out = (const float*)d_in[11];

    static int grid = 0;
    if (grid == 0){
        cudaFuncSetAttribute(brits_kernel, cudaFuncAttributeMaxDynamicSharedMemorySize, SMEMSZ);
        int occ = 1;
        cudaOccupancyMaxActiveBlocksPerMultiprocessor(&occ, brits_kernel, NTH, SMEMSZ);
        if (occ < 1) occ = 1;
        if (occ > 2) occ = 2;
        grid = 148 * occ;
    }
    init_kernel<<<512, 256>>>(W_ih0, W_hh0, W_ih1, W_hh1, W_out);
    brits_kernel<<<grid, NTH, SMEMSZ>>>(X, Msk, b_ih0, b_hh0, b_ih1, b_hh1,
                                        W_out, b_out, (float*)d_out);
}

// round 16
// speedup vs baseline: 1.5522x; 1.0478x over previous
#include <cuda_runtime.h>
#include <cuda_bf16.h>
#include <math.h>
#include <stdint.h>

#define BB 256
#define TT 256
#define DD 128
#define HH 512
#define G3 1536
#define NTH 256
typedef unsigned u32;
typedef __nv_bfloat16 bf;

__device__ float g_h[BB*HH];
__device__ float g_hp[BB*HH];
__device__ float g_gh0[BB*G3];
__device__ bf g_h_hi[BB*HH],  g_h_lo[BB*HH];
__device__ bf g_hp_hi[BB*HH], g_hp_lo[BB*HH];
__device__ bf g_imp_hi[BB*DD], g_imp_lo[BB*DD];
__device__ unsigned g_bar;
__device__ volatile unsigned g_rel;
__device__ bf wA_hi[1664*HH], wA_lo[1664*HH];  // [W_hh0 ; W_out]
__device__ bf wB_hi[G3*DD],   wB_lo[G3*DD];    // W_ih0 gate-blocked by 8
__device__ bf wC_hi[2048*HH], wC_lo[2048*HH];  // per 8-j block: [rc(8),zc(8),in(8),hn(8)]

__device__ __forceinline__ void splitw(float x, bf* hi, bf* lo){
    bf h = __float2bfloat16(x);
    *hi = h; *lo = __float2bfloat16(x - __bfloat162float(h));
}

__global__ void init_kernel(const float* W_ih0, const float* W_hh0,
                            const float* W_ih1, const float* W_hh1,
                            const float* W_out){
    int idx = blockIdx.x*blockDim.x + threadIdx.x;
    int gs  = gridDim.x*blockDim.x;
    if (idx == 0){ g_bar = 0u; g_rel = 0u; }
    for (int i = idx; i < BB*HH; i += gs){
        g_h[i] = 0.f; g_h_hi[i] = __float2bfloat16(0.f); g_h_lo[i] = __float2bfloat16(0.f);
    }
    for (int i = idx; i < 1664*HH; i += gs){
        int n = i/HH, k = i - n*HH;
        float x = (n < G3) ? W_hh0[(size_t)n*HH + k] : W_out[(size_t)(n-G3)*HH + k];
        splitw(x, &wA_hi[i], &wA_lo[i]);
    }
    for (int i = idx; i < G3*DD; i += gs){
        int q = i/DD, k = i - q*DD;
        int gi = q/24, w = q%24, gate = w>>3, j = gi*8 + (w&7);
        splitw(W_ih0[(size_t)(gate*HH + j)*DD + k], &wB_hi[i], &wB_lo[i]);
    }
    // cell-1 input == hidden -> combine r,z weights
    for (int i = idx; i < 2048*HH; i += gs){
        int q = i/HH, k = i - q*HH;
        int blk = q/32, w = q%32, gate = w>>3, jo = w&7;
        int j = blk*8 + jo;
        float x;
        if (gate == 0)      x = W_ih1[(size_t)j*HH + k]          + W_hh1[(size_t)j*HH + k];
        else if (gate == 1) x = W_ih1[(size_t)(HH + j)*HH + k]   + W_hh1[(size_t)(HH + j)*HH + k];
        else if (gate == 2) x = W_ih1[(size_t)(2*HH + j)*HH + k];
        else                x = W_hh1[(size_t)(2*HH + j)*HH + k];
        splitw(x, &wC_hi[i], &wC_lo[i]);
    }
}

__device__ __forceinline__ u32 s2u(const void* p){
    u32 a; asm("{ .reg .u64 t; cvta.to.shared.u64 t, %1; cvt.u32.u64 %0, t; }" : "=r"(a) : "l"(p));
    return a;
}
__device__ __forceinline__ void cpasync16(u32 dst, const void* src){
    asm volatile("cp.async.cg.shared.global [%0], [%1], 16;" :: "r"(dst), "l"(src));
}
#define CP_COMMIT() asm volatile("cp.async.commit_group;" ::: "memory")
#define CP_WAIT0()  asm volatile("cp.async.wait_group 0;" ::: "memory")
#define CP_WAIT1()  asm volatile("cp.async.wait_group 1;" ::: "memory")

__device__ __forceinline__ void mma_bf(float* d, u32 a0,u32 a1,u32 a2,u32 a3, u32 b0,u32 b1){
    asm volatile("mma.sync.aligned.m16n8k16.row.col.f32.bf16.bf16.f32 "
        "{%0,%1,%2,%3},{%4,%5,%6,%7},{%8,%9},{%0,%1,%2,%3};"
        : "+f"(d[0]),"+f"(d[1]),"+f"(d[2]),"+f"(d[3])
        : "r"(a0),"r"(a1),"r"(a2),"r"(a3),"r"(b0),"r"(b1));
}
__device__ __forceinline__ void ldsm4(u32* r, u32 a){
    asm volatile("ldmatrix.sync.aligned.m8n8.x4.shared.b16 {%0,%1,%2,%3}, [%4];"
        : "=r"(r[0]),"=r"(r[1]),"=r"(r[2]),"=r"(r[3]) : "r"(a));
}
__device__ __forceinline__ void ldsm2(u32* r, u32 a){
    asm volatile("ldmatrix.sync.aligned.m8n8.x2.shared.b16 {%0,%1}, [%2];"
        : "=r"(r[0]),"=r"(r[1]) : "r"(a));
}

__device__ __forceinline__ void grid_barrier(unsigned &target){
    __syncthreads();
    target += gridDim.x;
    if (threadIdx.x == 0){
        __threadfence();
        unsigned old = atomicAdd(&g_bar, 1u);
        if (old == target - 1u){
            g_rel = target;
            __threadfence();
        } else {
            int sp = 0;
            while (g_rel < target) if (++sp > 512) __nanosleep(64);
        }
    }
    __syncthreads();
}
__device__ __forceinline__ float sigf(float x){ return 1.f/(1.f+expf(-x)); }

// ---- smem: 3-buffer ring (depth-2 prefetch) + resident B weights
#define AH_OFF  0u
#define AL_OFF  9216u
#define WH_OFF  18432u
#define WL_OFF  25344u
#define BUF_SZ  32256u
#define RESB_HI 96768u
#define RESB_LO 103680u
#define SMEMSZ  110592

extern __shared__ __align__(16) char smc[];

template<int WROWS>
__device__ __forceinline__ void load_chunk(int buf, const bf* Ahi, const bf* Alo, int lda,
                                           const bf* W1, const bf* W2, int KW, int kc)
{
    const int tid = threadIdx.x;
    const u32 b = s2u(smc) + (u32)buf*BUF_SZ;
    int seg = tid;
    #pragma unroll
    for (int i = 0; i < 2; i++, seg += NTH){
        int r = seg >> 3, c = seg & 7;
        u32 d = b + r*144 + c*16;
        cpasync16(d + AH_OFF, Ahi + (size_t)r*lda + kc + c*8);
        cpasync16(d + AL_OFF, Alo + (size_t)r*lda + kc + c*8);
    }
    if (WROWS > 0){
        for (int s = tid; s < WROWS*8; s += NTH){
            int r = s >> 3, c = s & 7;
            u32 d = b + r*144 + c*16;
            cpasync16(d + WH_OFF, W1 + (size_t)r*KW + kc + c*8);
            cpasync16(d + WL_OFF, W2 + (size_t)r*KW + kc + c*8);
        }
    }
}

// 3 independent accumulator chains per n-fragment
template<int NFR>
__device__ __forceinline__ void mma_chunk(u32 sAh, u32 sAl, u32 sWh, u32 sWl,
                                          int wm, int wn,
                                          float (*accH)[4], float (*accM1)[4], float (*accM2)[4])
{
    const int lane = threadIdx.x & 31;
    const int lg = lane & 7, grp = lane >> 3;
    const u32 arow = (u32)(wm + lg + (grp & 1)*8) * 144 + ((grp >> 1) & 1)*16;
    const int l16 = lane & 15;
    const u32 brow0 = (u32)(l16 & 7) * 144 + (u32)(l16 >> 3) * 16;
    #pragma unroll
    for (int k16 = 0; k16 < 4; k16++){
        u32 ah[4], al[4];
        ldsm4(ah, sAh + arow + k16*32);
        ldsm4(al, sAl + arow + k16*32);
        #pragma unroll
        for (int nf = 0; nf < NFR; nf++){
            u32 boff = brow0 + (u32)(wn + 8*nf)*144 + k16*32;
            u32 bh[2], bl[2];
            ldsm2(bh, sWh + boff);
            ldsm2(bl, sWl + boff);
            mma_bf(accH[nf],  ah[0],ah[1],ah[2],ah[3], bh[0],bh[1]);
            mma_bf(accM1[nf], ah[0],ah[1],ah[2],ah[3], bl[0],bl[1]);
            mma_bf(accM2[nf], al[0],al[1],al[2],al[3], bh[0],bh[1]);
        }
    }
}

// Ring-3, prefetch depth 2, one wait + one sync per chunk.
template<int NC, int WROWS, int NFR>
__device__ __forceinline__ void gemm_run(const bf* Ahi, const bf* Alo, int lda,
    const bf* W1, const bf* W2, int KW, int wm, int wn,
    float (*accH)[4], float (*accM1)[4], float (*accM2)[4])
{
    #pragma unroll
    for (int n = 0; n < NFR; n++)
        #pragma unroll
        for (int q = 0; q < 4; q++){ accH[n][q] = 0.f; accM1[n][q] = 0.f; accM2[n][q] = 0.f; }

    load_chunk<WROWS>(0, Ahi, Alo, lda, W1, W2, KW, 0);
    CP_COMMIT();
    if (NC > 1){
        load_chunk<WROWS>(1, Ahi, Alo, lda, W1, W2, KW, 64);
        CP_COMMIT();
    }
    const u32 sb = s2u(smc);
    for (int ch = 0; ch < NC; ch++){
        if (ch + 1 < NC) CP_WAIT1(); else CP_WAIT0();
        __syncthreads();
        if (ch + 2 < NC){
            load_chunk<WROWS>((ch+2)%3, Ahi, Alo, lda, W1, W2, KW, (ch+2)*64);
            CP_COMMIT();
        }
        const u32 b = sb + (u32)(ch%3)*BUF_SZ;
        mma_chunk<NFR>(b+AH_OFF, b+AL_OFF, b+WH_OFF, b+WL_OFF, wm, wn, accH, accM1, accM2);
    }
}

__global__ void __launch_bounds__(NTH, 2) brits_kernel(
    const float* __restrict__ X,     const float* __restrict__ Msk,
    const float* __restrict__ b_ih0, const float* __restrict__ b_hh0,
    const float* __restrict__ b_ih1, const float* __restrict__ b_hh1,
    const float* __restrict__ W_out, const float* __restrict__ b_out,
    float* __restrict__ out)
{
    const int tid = threadIdx.x, wid = tid >> 5, lane = tid & 31, bx = blockIdx.x;
    const int g = lane >> 2, t = lane & 3;
    const int half = wid & 1;
    const int wm = (wid >> 1) * 16;
    float* xbuf = (float*)smc;            // aliases ring buf0 (dead at epilogue)

    float* pre_o = out;
    float* out_o = out + (size_t)BB*TT*DD;
    float* hf_o  = out + (size_t)2*BB*TT*DD;
    float* hid_o = hf_o + (size_t)BB*HH;

    unsigned target = 0;
    const int gs   = gridDim.x * blockDim.x;
    const int gtid = bx * blockDim.x + tid;
    const u32 sb = s2u(smc);

    for (int ts = 0; ts < TT; ts++){
        // ---- A: [gh0 | est] = h @ [W_hh0;W_out]^T. 208 tiles 64m x 32n, K=512
        for (int tile = bx; tile < 208; tile += gridDim.x){
            const int m0 = (tile / 52) * 64, n0 = (tile % 52) * 32;
            const int wn = half * 16;
            float accH[2][4], accM1[2][4], accM2[2][4];
            gemm_run<8,32,2>(g_h_hi + (size_t)m0*HH, g_h_lo + (size_t)m0*HH, HH,
                             wA_hi + (size_t)n0*HH, wA_lo + (size_t)n0*HH, HH,
                             wm, wn, accH, accM1, accM2);
            #pragma unroll
            for (int nf = 0; nf < 2; nf++)
                #pragma unroll
                for (int rh = 0; rh < 2; rh++)
                    #pragma unroll
                    for (int d = 0; d < 2; d++){
                        int m = m0 + wm + g + 8*rh;
                        int n = n0 + wn + 8*nf + 2*t + d;
                        int q = rh*2 + d;
                        float v = accH[nf][q] + accM1[nf][q] + accM2[nf][q];
                        if (n < G3) g_gh0[m*G3 + n] = v + b_hh0[n];
                        else {
                            int dd = n - G3;
                            float est = v + b_out[dd];
                            int io = (m*TT + ts)*DD + dd;
                            pre_o[io] = est;
                            float imp = est + Msk[io] * (X[io] - est);
                            bf hi = __float2bfloat16(imp);
                            g_imp_hi[m*DD + dd] = hi;
                            g_imp_lo[m*DD + dd] = __float2bfloat16(imp - __bfloat162float(hi));
                            if (ts > 0) out_o[io - DD] = imp;
                        }
                    }
        }
        grid_barrier(target);

        // ---- B: fused cell-0. 256 tiles 64m x 24n, K=128 split across halves. Resident W.
        for (int tile = bx; tile < 256; tile += gridDim.x){
            const int m0 = (tile / 64) * 64, jt = tile % 64, j0 = jt * 8;
            const int qB = jt * 24;
            for (int s = tid; s < 2*24*8; s += NTH){
                int ch = s / 192, r = (s >> 3) % 24, c = s & 7;
                *(uint4*)(smc + RESB_HI + (ch*24 + r)*144 + c*16) =
                    __ldg((const uint4*)(wB_hi + (size_t)(qB + r)*DD + ch*64 + c*8));
                *(uint4*)(smc + RESB_LO + (ch*24 + r)*144 + c*16) =
                    __ldg((const uint4*)(wB_lo + (size_t)(qB + r)*DD + ch*64 + c*8));
            }
            load_chunk<0>(0, g_imp_hi + (size_t)m0*DD, g_imp_lo + (size_t)m0*DD, DD,
                          (const bf*)0, (const bf*)0, DD, 0);
            load_chunk<0>(1, g_imp_hi + (size_t)m0*DD, g_imp_lo + (size_t)m0*DD, DD,
                          (const bf*)0, (const bf*)0, DD, 64);
            CP_COMMIT(); CP_WAIT0();
            __syncthreads();
            float accH[3][4], accM1[3][4], accM2[3][4];
            #pragma unroll
            for (int n = 0; n < 3; n++)
                #pragma unroll
                for (int q = 0; q < 4; q++){ accH[n][q]=0.f; accM1[n][q]=0.f; accM2[n][q]=0.f; }
            const u32 b = sb + (u32)half*BUF_SZ;
            mma_chunk<3>(b+AH_OFF, b+AL_OFF,
                         sb + RESB_HI + (u32)half*24*144, sb + RESB_LO + (u32)half*24*144,
                         wm, 0, accH, accM1, accM2);
            __syncthreads();
            if (half == 1)
                #pragma unroll
                for (int nf = 0; nf < 3; nf++)
                    #pragma unroll
                    for (int rh = 0; rh < 2; rh++)
                        #pragma unroll
                        for (int d = 0; d < 2; d++){
                            int q = rh*2 + d;
                            xbuf[(wm + g + 8*rh)*24 + nf*8 + 2*t + d] =
                                accH[nf][q] + accM1[nf][q] + accM2[nf][q];
                        }
            __syncthreads();
            if (half == 0)
                #pragma unroll
                for (int rh = 0; rh < 2; rh++)
                    #pragma unroll
                    for (int d = 0; d < 2; d++){
                        int m = m0 + wm + g + 8*rh;
                        int j = j0 + 2*t + d;
                        int q = rh*2 + d;
                        int xb = (wm + g + 8*rh)*24 + 2*t + d;
                        float gr = accH[0][q]+accM1[0][q]+accM2[0][q] + xbuf[xb]    + b_ih0[j]      + __ldcg(&g_gh0[m*G3 + j]);
                        float gz = accH[1][q]+accM1[1][q]+accM2[1][q] + xbuf[xb+8]  + b_ih0[HH + j] + __ldcg(&g_gh0[m*G3 + HH + j]);
                        float gn = accH[2][q]+accM1[2][q]+accM2[2][q] + xbuf[xb+16] + b_ih0[2*HH + j];
                        float hn = __ldcg(&g_gh0[m*G3 + 2*HH + j]);
                        float r = sigf(gr), z = sigf(gz);
                        float nn = tanhf(gn + r * hn);
                        float hp = (1.f - z) * nn + z * __ldcg(&g_h[m*HH + j]);
                        g_hp[m*HH + j] = hp;
                        bf hi = __float2bfloat16(hp);
                        g_hp_hi[m*HH + j] = hi;
                        g_hp_lo[m*HH + j] = __float2bfloat16(hp - __bfloat162float(hi));
                    }
            __syncthreads();
        }
        grid_barrier(target);

        // ---- C: fused cell-1 (combined r/z weights). 256 tiles 64m x 32n, K=512.
        for (int tile = bx; tile < 256; tile += gridDim.x){
            const int m0 = (tile >> 6) * 64, jblk = tile & 63;
            const int j0 = jblk * 8, q0 = jblk * 32;
            const int wn = half * 16;
            float accH[2][4], accM1[2][4], accM2[2][4];
            gemm_run<8,32,2>(g_hp_hi + (size_t)m0*HH, g_hp_lo + (size_t)m0*HH, HH,
                             wC_hi + (size_t)q0*HH, wC_lo + (size_t)q0*HH, HH,
                             wm, wn, accH, accM1, accM2);
            if (half == 1)   // rows 16..31: in (nf=0), hn (nf=1)
                #pragma unroll
                for (int rh = 0; rh < 2; rh++)
                    #pragma unroll
                    for (int d = 0; d < 2; d++){
                        int ml = wm + g + 8*rh, jo = 2*t + d, q = rh*2 + d;
                        float* xp = &xbuf[(ml*8 + jo)*2];
                        xp[0] = accH[0][q] + accM1[0][q] + accM2[0][q];
                        xp[1] = accH[1][q] + accM1[1][q] + accM2[1][q];
                    }
            __syncthreads();
            if (half == 0)   // rows 0..15: rc (nf=0), zc (nf=1)
                #pragma unroll
                for (int rh = 0; rh < 2; rh++)
                    #pragma unroll
                    for (int d = 0; d < 2; d++){
                        int ml = wm + g + 8*rh, m = m0 + ml;
                        int jo = 2*t + d, j = j0 + jo;
                        int q = rh*2 + d;
                        const float* xp = &xbuf[(ml*8 + jo)*2];
                        float rcv = accH[0][q] + accM1[0][q] + accM2[0][q];
                        float zcv = accH[1][q] + accM1[1][q] + accM2[1][q];
                        float r = sigf(rcv + b_ih1[j] + b_hh1[j]);
                        float z = sigf(zcv + b_ih1[HH + j] + b_hh1[HH + j]);
                        float nn = tanhf(xp[0] + b_ih1[2*HH + j] + r * (xp[1] + b_hh1[2*HH + j]));
                        float hnew = (1.f - z) * nn + z * __ldcg(&g_hp[m*HH + j]);
                        g_h[m*HH + j] = hnew;
                        bf hi = __float2bfloat16(hnew);
                        g_h_hi[m*HH + j] = hi;
                        g_h_lo[m*HH + j] = __float2bfloat16(hnew - __bfloat162float(hi));
                        hid_o[((size_t)m*TT + ts)*HH + j] = hnew;
                    }
            __syncthreads();
        }
        grid_barrier(target);
    }

    // tail
    for (int idx = gtid; idx < BB*DD; idx += gs){
        int b = idx >> 7, d = idx & 127;
        const float4* hv = (const float4*)(g_h + (size_t)b*HH);
        const float4* wv = (const float4*)(W_out + (size_t)d*HH);
        float s = b_out[d];
        #pragma unroll 8
        for (int q = 0; q < HH/4; q++){
            float4 a = __ldcg(&hv[q]); float4 w = __ldg(&wv[q]);
            s += a.x*w.x + a.y*w.y + a.z*w.z + a.w*w.w;
        }
        out_o[((size_t)b*TT + (TT-1))*DD + d] = s;
    }
    for (int idx = gtid; idx < BB*HH; idx += gs)
        hf_o[idx] = __ldcg(&g_h[idx]);
}

extern "C" void kernel_launch(void* const* d_in, const int* in_sizes, int n_in,
                              void* d_out, int out_size) {
    const float* X     = (const float*)d_in[0];
    const float* Msk   = (const float*)d_in[1];
    const float* W_ih0 = (const float*)d_in[2];
    const float* W_hh0 = (const float*)d_in[3];
    const float* b_ih0 = (const float*)d_in[4];
    const float* b_hh0 = (const float*)d_in[5];
    const float* W_ih1 = (const float*)d_in[6];
    const float* W_hh1 = (const float*)d_in[7];
    const float* b_ih1 = (const float*)d_in[8];
    const float* b_hh1 = (const float*)d_in[9];
    const float* W_out = (const float*)d_in[10];
    const float* b_out = (const float*)d_in[11];

    static int grid = 0;
    if (grid == 0){
        cudaFuncSetAttribute(brits_kernel, cudaFuncAttributeMaxDynamicSharedMemorySize, SMEMSZ);
        int occ = 1;
        cudaOccupancyMaxActiveBlocksPerMultiprocessor(&occ, brits_kernel, NTH, SMEMSZ);
        if (occ < 1) occ = 1;
        if (occ > 2) occ = 2;
        grid = 148 * occ;
    }
    init_kernel<<<512, 256>>>(W_ih0, W_hh0, W_ih1, W_hh1, W_out);
    brits_kernel<<<grid, NTH, SMEMSZ>>>(X, Msk, b_ih0, b_hh0, b_ih1, b_hh1,
                                        W_out, b_out, (float*)d_out);
}

// round 17
// speedup vs baseline: 1.6320x; 1.0514x over previous
#include <cuda_runtime.h>
#include <cuda_bf16.h>
#include <math.h>
#include <stdint.h>

#define BB 256
#define TT 256
#define DD 128
#define HH 512
#define G3 1536
#define NTH 128
typedef unsigned u32;
typedef __nv_bfloat16 bf;

__device__ float g_h[BB*HH];
__device__ float g_hp[BB*HH];
__device__ float g_gh0[BB*G3];
__device__ bf g_h_hi[BB*HH],  g_h_lo[BB*HH];
__device__ bf g_hp_hi[BB*HH], g_hp_lo[BB*HH];
__device__ bf g_imp_hi[BB*DD], g_imp_lo[BB*DD];
__device__ unsigned g_bar;
__device__ volatile unsigned g_rel;
__device__ bf wA_hi[1664*HH], wA_lo[1664*HH];  // [W_hh0 ; W_out]
__device__ bf wB_hi[G3*DD],   wB_lo[G3*DD];    // W_ih0: per 8-j block, 3 gates x 8 j
__device__ bf wC_hi[2048*HH], wC_lo[2048*HH];  // per 8-j block: [rc(8),zc(8),in(8),hn(8)]

__device__ __forceinline__ void splitw(float x, bf* hi, bf* lo){
    bf h = __float2bfloat16(x);
    *hi = h; *lo = __float2bfloat16(x - __bfloat162float(h));
}

__global__ void init_kernel(const float* W_ih0, const float* W_hh0,
                            const float* W_ih1, const float* W_hh1,
                            const float* W_out){
    int idx = blockIdx.x*blockDim.x + threadIdx.x;
    int gs  = gridDim.x*blockDim.x;
    if (idx == 0){ g_bar = 0u; g_rel = 0u; }
    for (int i = idx; i < BB*HH; i += gs){
        g_h[i] = 0.f; g_h_hi[i] = __float2bfloat16(0.f); g_h_lo[i] = __float2bfloat16(0.f);
    }
    for (int i = idx; i < 1664*HH; i += gs){
        int n = i/HH, k = i - n*HH;
        float x = (n < G3) ? W_hh0[(size_t)n*HH + k] : W_out[(size_t)(n-G3)*HH + k];
        splitw(x, &wA_hi[i], &wA_lo[i]);
    }
    for (int i = idx; i < G3*DD; i += gs){
        int q = i/DD, k = i - q*DD;
        int gi = q/24, w = q%24, gate = w>>3, j = gi*8 + (w&7);
        splitw(W_ih0[(size_t)(gate*HH + j)*DD + k], &wB_hi[i], &wB_lo[i]);
    }
    // cell-1 input == hidden -> combined r,z weights
    for (int i = idx; i < 2048*HH; i += gs){
        int q = i/HH, k = i - q*HH;
        int blk = q/32, w = q%32, gate = w>>3, jo = w&7;
        int j = blk*8 + jo;
        float x;
        if (gate == 0)      x = W_ih1[(size_t)j*HH + k]          + W_hh1[(size_t)j*HH + k];
        else if (gate == 1) x = W_ih1[(size_t)(HH + j)*HH + k]   + W_hh1[(size_t)(HH + j)*HH + k];
        else if (gate == 2) x = W_ih1[(size_t)(2*HH + j)*HH + k];
        else                x = W_hh1[(size_t)(2*HH + j)*HH + k];
        splitw(x, &wC_hi[i], &wC_lo[i]);
    }
}

__device__ __forceinline__ u32 s2u(const void* p){
    u32 a; asm("{ .reg .u64 t; cvta.to.shared.u64 t, %1; cvt.u32.u64 %0, t; }" : "=r"(a) : "l"(p));
    return a;
}
__device__ __forceinline__ void cpasync16(u32 dst, const void* src){
    asm volatile("cp.async.cg.shared.global [%0], [%1], 16;" :: "r"(dst), "l"(src));
}
#define CP_COMMIT() asm volatile("cp.async.commit_group;" ::: "memory")
#define CP_WAIT0()  asm volatile("cp.async.wait_group 0;" ::: "memory")
#define CP_WAIT1()  asm volatile("cp.async.wait_group 1;" ::: "memory")

__device__ __forceinline__ void mma_bf(float* d, u32 a0,u32 a1,u32 a2,u32 a3, u32 b0,u32 b1){
    asm volatile("mma.sync.aligned.m16n8k16.row.col.f32.bf16.bf16.f32 "
        "{%0,%1,%2,%3},{%4,%5,%6,%7},{%8,%9},{%0,%1,%2,%3};"
        : "+f"(d[0]),"+f"(d[1]),"+f"(d[2]),"+f"(d[3])
        : "r"(a0),"r"(a1),"r"(a2),"r"(a3),"r"(b0),"r"(b1));
}
__device__ __forceinline__ void ldsm4(u32* r, u32 a){
    asm volatile("ldmatrix.sync.aligned.m8n8.x4.shared.b16 {%0,%1,%2,%3}, [%4];"
        : "=r"(r[0]),"=r"(r[1]),"=r"(r[2]),"=r"(r[3]) : "r"(a));
}
__device__ __forceinline__ void ldsm2(u32* r, u32 a){
    asm volatile("ldmatrix.sync.aligned.m8n8.x2.shared.b16 {%0,%1}, [%2];"
        : "=r"(r[0]),"=r"(r[1]) : "r"(a));
}

__device__ __forceinline__ void grid_barrier(unsigned &target){
    __syncthreads();
    target += gridDim.x;
    if (threadIdx.x == 0){
        __threadfence();
        unsigned old = atomicAdd(&g_bar, 1u);
        if (old == target - 1u){
            g_rel = target;
            __threadfence();
        } else {
            int sp = 0;
            while (g_rel < target) if (++sp > 512) __nanosleep(64);
        }
    }
    __syncthreads();
}
__device__ __forceinline__ float sigf(float x){ return 1.f/(1.f+expf(-x)); }

// ---- smem: 3-buffer ring, 32-row tiles (A hi/lo + W hi/lo per buffer)
#define AH_OFF  0u
#define AL_OFF  4608u
#define WH_OFF  9216u
#define WL_OFF  13824u
#define BUF_SZ  18432u
#define SMEMSZ  55296

extern __shared__ __align__(16) char smc[];

// one K64 chunk: A 32 rows hi/lo (+ W rows hi/lo)
template<int WROWS>
__device__ __forceinline__ void load_chunk(int buf, const bf* Ahi, const bf* Alo, int lda,
                                           const bf* W1, const bf* W2, int KW, int kc)
{
    const int tid = threadIdx.x;
    const u32 b = s2u(smc) + (u32)buf*BUF_SZ;
    int seg = tid;
    #pragma unroll
    for (int i = 0; i < 2; i++, seg += NTH){   // 256 segs = 32 rows x 8
        int r = seg >> 3, c = seg & 7;
        u32 d = b + r*144 + c*16;
        cpasync16(d + AH_OFF, Ahi + (size_t)r*lda + kc + c*8);
        cpasync16(d + AL_OFF, Alo + (size_t)r*lda + kc + c*8);
    }
    if (WROWS > 0){
        for (int s = tid; s < WROWS*8; s += NTH){
            int r = s >> 3, c = s & 7;
            u32 d = b + r*144 + c*16;
            cpasync16(d + WH_OFF, W1 + (size_t)r*KW + kc + c*8);
            cpasync16(d + WL_OFF, W2 + (size_t)r*KW + kc + c*8);
        }
    }
}

// 3 independent accumulator chains per n-fragment
template<int NFR>
__device__ __forceinline__ void mma_chunk(u32 sAh, u32 sAl, u32 sWh, u32 sWl,
                                          int wm, int wn,
                                          float (*accH)[4], float (*accM1)[4], float (*accM2)[4])
{
    const int lane = threadIdx.x & 31;
    const int lg = lane & 7, grp = lane >> 3;
    const u32 arow = (u32)(wm + lg + (grp & 1)*8) * 144 + ((grp >> 1) & 1)*16;
    const int l16 = lane & 15;
    const u32 brow0 = (u32)(l16 & 7) * 144 + (u32)(l16 >> 3) * 16;
    #pragma unroll
    for (int k16 = 0; k16 < 4; k16++){
        u32 ah[4], al[4];
        ldsm4(ah, sAh + arow + k16*32);
        ldsm4(al, sAl + arow + k16*32);
        #pragma unroll
        for (int nf = 0; nf < NFR; nf++){
            u32 boff = brow0 + (u32)(wn + 8*nf)*144 + k16*32;
            u32 bh[2], bl[2];
            ldsm2(bh, sWh + boff);
            ldsm2(bl, sWl + boff);
            mma_bf(accH[nf],  ah[0],ah[1],ah[2],ah[3], bh[0],bh[1]);
            mma_bf(accM1[nf], ah[0],ah[1],ah[2],ah[3], bl[0],bl[1]);
            mma_bf(accM2[nf], al[0],al[1],al[2],al[3], bh[0],bh[1]);
        }
    }
}

// Ring-3, prefetch depth 2, one wait + one sync per chunk.
template<int NC, int WROWS, int NFR>
__device__ __forceinline__ void gemm_run(const bf* Ahi, const bf* Alo, int lda,
    const bf* W1, const bf* W2, int KW, int wm, int wn,
    float (*accH)[4], float (*accM1)[4], float (*accM2)[4])
{
    #pragma unroll
    for (int n = 0; n < NFR; n++)
        #pragma unroll
        for (int q = 0; q < 4; q++){ accH[n][q] = 0.f; accM1[n][q] = 0.f; accM2[n][q] = 0.f; }

    load_chunk<WROWS>(0, Ahi, Alo, lda, W1, W2, KW, 0);
    CP_COMMIT();
    if (NC > 1){
        load_chunk<WROWS>(1, Ahi, Alo, lda, W1, W2, KW, 64);
        CP_COMMIT();
    }
    const u32 sb = s2u(smc);
    for (int ch = 0; ch < NC; ch++){
        if (ch + 1 < NC) CP_WAIT1(); else CP_WAIT0();
        __syncthreads();
        if (ch + 2 < NC){
            load_chunk<WROWS>((ch+2)%3, Ahi, Alo, lda, W1, W2, KW, (ch+2)*64);
            CP_COMMIT();
        }
        const u32 b = sb + (u32)(ch%3)*BUF_SZ;
        mma_chunk<NFR>(b+AH_OFF, b+AL_OFF, b+WH_OFF, b+WL_OFF, wm, wn, accH, accM1, accM2);
    }
}

__global__ void __launch_bounds__(NTH, 4) brits_kernel(
    const float* __restrict__ X,     const float* __restrict__ Msk,
    const float* __restrict__ b_ih0, const float* __restrict__ b_hh0,
    const float* __restrict__ b_ih1, const float* __restrict__ b_hh1,
    const float* __restrict__ W_out, const float* __restrict__ b_out,
    float* __restrict__ out)
{
    const int tid = threadIdx.x, wid = tid >> 5, lane = tid & 31, bx = blockIdx.x;
    const int g = lane >> 2, t = lane & 3;
    const int half = wid >> 1;            // n-half / K-half
    const int wm = (wid & 1) * 16;        // m-frag base within 32-row tile
    float* xbuf = (float*)smc;            // aliases ring buf0 (dead at epilogue)

    float* pre_o = out;
    float* out_o = out + (size_t)BB*TT*DD;
    float* hf_o  = out + (size_t)2*BB*TT*DD;
    float* hid_o = hf_o + (size_t)BB*HH;

    unsigned target = 0;
    const int gs   = gridDim.x * blockDim.x;
    const int gtid = bx * blockDim.x + tid;
    const u32 sb = s2u(smc);

    for (int ts = 0; ts < TT; ts++){
        // ---- A: [gh0 | est] = h @ [W_hh0;W_out]^T. 416 tiles 32m x 32n, K=512
        for (int tile = bx; tile < 416; tile += gridDim.x){
            const int m0 = (tile / 52) * 32, n0 = (tile % 52) * 32;
            const int wn = half * 16;
            float accH[2][4], accM1[2][4], accM2[2][4];
            gemm_run<8,32,2>(g_h_hi + (size_t)m0*HH, g_h_lo + (size_t)m0*HH, HH,
                             wA_hi + (size_t)n0*HH, wA_lo + (size_t)n0*HH, HH,
                             wm, wn, accH, accM1, accM2);
            #pragma unroll
            for (int nf = 0; nf < 2; nf++)
                #pragma unroll
                for (int rh = 0; rh < 2; rh++)
                    #pragma unroll
                    for (int d = 0; d < 2; d++){
                        int m = m0 + wm + g + 8*rh;
                        int n = n0 + wn + 8*nf + 2*t + d;
                        int q = rh*2 + d;
                        float v = accH[nf][q] + accM1[nf][q] + accM2[nf][q];
                        if (n < G3) g_gh0[m*G3 + n] = v + b_hh0[n];
                        else {
                            int dd = n - G3;
                            float est = v + b_out[dd];
                            int io = (m*TT + ts)*DD + dd;
                            pre_o[io] = est;
                            float imp = est + Msk[io] * (X[io] - est);
                            bf hi = __float2bfloat16(imp);
                            g_imp_hi[m*DD + dd] = hi;
                            g_imp_lo[m*DD + dd] = __float2bfloat16(imp - __bfloat162float(hi));
                            if (ts > 0) out_o[io - DD] = imp;
                        }
                    }
        }
        grid_barrier(target);

        // ---- B: fused cell-0. 512 tiles 32m x 24n (3 gates x 8 j), K=128 split across halves
        for (int tile = bx; tile < 512; tile += gridDim.x){
            const int m0 = (tile >> 6) * 32, jt = tile & 63, j0 = jt * 8;
            load_chunk<24>(0, g_imp_hi + (size_t)m0*DD, g_imp_lo + (size_t)m0*DD, DD,
                           wB_hi + (size_t)jt*24*DD, wB_lo + (size_t)jt*24*DD, DD, 0);
            CP_COMMIT();
            load_chunk<24>(1, g_imp_hi + (size_t)m0*DD, g_imp_lo + (size_t)m0*DD, DD,
                           wB_hi + (size_t)jt*24*DD, wB_lo + (size_t)jt*24*DD, DD, 64);
            CP_COMMIT(); CP_WAIT0();
            __syncthreads();
            float accH[3][4], accM1[3][4], accM2[3][4];
            #pragma unroll
            for (int n = 0; n < 3; n++)
                #pragma unroll
                for (int q = 0; q < 4; q++){ accH[n][q]=0.f; accM1[n][q]=0.f; accM2[n][q]=0.f; }
            const u32 b = sb + (u32)half*BUF_SZ;
            mma_chunk<3>(b+AH_OFF, b+AL_OFF, b+WH_OFF, b+WL_OFF, wm, 0, accH, accM1, accM2);
            __syncthreads();
            if (half == 1)
                #pragma unroll
                for (int nf = 0; nf < 3; nf++)
                    #pragma unroll
                    for (int rh = 0; rh < 2; rh++)
                        #pragma unroll
                        for (int d = 0; d < 2; d++){
                            int q = rh*2 + d;
                            xbuf[(wm + g + 8*rh)*24 + nf*8 + 2*t + d] =
                                accH[nf][q] + accM1[nf][q] + accM2[nf][q];
                        }
            __syncthreads();
            if (half == 0)
                #pragma unroll
                for (int rh = 0; rh < 2; rh++)
                    #pragma unroll
                    for (int d = 0; d < 2; d++){
                        int m = m0 + wm + g + 8*rh;
                        int j = j0 + 2*t + d;
                        int q = rh*2 + d;
                        int xb = (wm + g + 8*rh)*24 + 2*t + d;
                        float gr = accH[0][q]+accM1[0][q]+accM2[0][q] + xbuf[xb]    + b_ih0[j]      + __ldcg(&g_gh0[m*G3 + j]);
                        float gz = accH[1][q]+accM1[1][q]+accM2[1][q] + xbuf[xb+8]  + b_ih0[HH + j] + __ldcg(&g_gh0[m*G3 + HH + j]);
                        float gn = accH[2][q]+accM1[2][q]+accM2[2][q] + xbuf[xb+16] + b_ih0[2*HH + j];
                        float hn = __ldcg(&g_gh0[m*G3 + 2*HH + j]);
                        float r = sigf(gr), z = sigf(gz);
                        float nn = tanhf(gn + r * hn);
                        float hp = (1.f - z) * nn + z * __ldcg(&g_h[m*HH + j]);
                        g_hp[m*HH + j] = hp;
                        bf hi = __float2bfloat16(hp);
                        g_hp_hi[m*HH + j] = hi;
                        g_hp_lo[m*HH + j] = __float2bfloat16(hp - __bfloat162float(hi));
                    }
            __syncthreads();
        }
        grid_barrier(target);

        // ---- C: fused cell-1 (combined r/z weights). 512 tiles 32m x 32n, K=512
        for (int tile = bx; tile < 512; tile += gridDim.x){
            const int m0 = (tile >> 6) * 32, jblk = tile & 63;
            const int j0 = jblk * 8, q0 = jblk * 32;
            const int wn = half * 16;
            float accH[2][4], accM1[2][4], accM2[2][4];
            gemm_run<8,32,2>(g_hp_hi + (size_t)m0*HH, g_hp_lo + (size_t)m0*HH, HH,
                             wC_hi + (size_t)q0*HH, wC_lo + (size_t)q0*HH, HH,
                             wm, wn, accH, accM1, accM2);
            if (half == 1)   // rows 16..31: in (nf=0), hn (nf=1)
                #pragma unroll
                for (int rh = 0; rh < 2; rh++)
                    #pragma unroll
                    for (int d = 0; d < 2; d++){
                        int ml = wm + g + 8*rh, jo = 2*t + d, q = rh*2 + d;
                        float* xp = &xbuf[(ml*8 + jo)*2];
                        xp[0] = accH[0][q] + accM1[0][q] + accM2[0][q];
                        xp[1] = accH[1][q] + accM1[1][q] + accM2[1][q];
                    }
            __syncthreads();
            if (half == 0)   // rows 0..15: rc (nf=0), zc (nf=1)
                #pragma unroll
                for (int rh = 0; rh < 2; rh++)
                    #pragma unroll
                    for (int d = 0; d < 2; d++){
                        int ml = wm + g + 8*rh, m = m0 + ml;
                        int jo = 2*t + d, j = j0 + jo;
                        int q = rh*2 + d;
                        const float* xp = &xbuf[(ml*8 + jo)*2];
                        float rcv = accH[0][q] + accM1[0][q] + accM2[0][q];
                        float zcv = accH[1][q] + accM1[1][q] + accM2[1][q];
                        float r = sigf(rcv + b_ih1[j] + b_hh1[j]);
                        float z = sigf(zcv + b_ih1[HH + j] + b_hh1[HH + j]);
                        float nn = tanhf(xp[0] + b_ih1[2*HH + j] + r * (xp[1] + b_hh1[2*HH + j]));
                        float hnew = (1.f - z) * nn + z * __ldcg(&g_hp[m*HH + j]);
                        g_h[m*HH + j] = hnew;
                        bf hi = __float2bfloat16(hnew);
                        g_h_hi[m*HH + j] = hi;
                        g_h_lo[m*HH + j] = __float2bfloat16(hnew - __bfloat162float(hi));
                        hid_o[((size_t)m*TT + ts)*HH + j] = hnew;
                    }
            __syncthreads();
        }
        grid_barrier(target);
    }

    // tail
    for (int idx = gtid; idx < BB*DD; idx += gs){
        int b = idx >> 7, d = idx & 127;
        const float4* hv = (const float4*)(g_h + (size_t)b*HH);
        const float4* wv = (const float4*)(W_out + (size_t)d*HH);
        float s = b_out[d];
        #pragma unroll 8
        for (int q = 0; q < HH/4; q++){
            float4 a = __ldcg(&hv[q]); float4 w = __ldg(&wv[q]);
            s += a.x*w.x + a.y*w.y + a.z*w.z + a.w*w.w;
        }
        out_o[((size_t)b*TT + (TT-1))*DD + d] = s;
    }
    for (int idx = gtid; idx < BB*HH; idx += gs)
        hf_o[idx] = __ldcg(&g_h[idx]);
}

extern "C" void kernel_launch(void* const* d_in, const int* in_sizes, int n_in,
                              void* d_out, int out_size) {
    const float* X     = (const float*)d_in[0];
    const float* Msk   = (const float*)d_in[1];
    const float* W_ih0 = (const float*)d_in[2];
    const float* W_hh0 = (const float*)d_in[3];
    const float* b_ih0 = (const float*)d_in[4];
    const float* b_hh0 = (const float*)d_in[5];
    const float* W_ih1 = (const float*)d_in[6];
    const float* W_hh1 = (const float*)d_in[7];
    const float* b_ih1 = (const float*)d_in[8];
    const float* b_hh1 = (const float*)d_in[9];
    const float* W_out = (const float*)d_in[10];
    const float* b_out = (const float*)d_in[11];

    static int grid = 0;
    if (grid == 0){
        cudaFuncSetAttribute(brits_kernel, cudaFuncAttributeMaxDynamicSharedMemorySize, SMEMSZ);
        int occ = 1;
        cudaOccupancyMaxActiveBlocksPerMultiprocessor(&occ, brits_kernel, NTH, SMEMSZ);
        if (occ < 1) occ = 1;
        if (occ > 4) occ = 4;
        grid = 148 * occ;
    }
    init_kernel<<<512, 256>>>(W_ih0, W_hh0, W_ih1, W_hh1, W_out);
    brits_kernel<<<grid, NTH, SMEMSZ>>>(X, Msk, b_ih0, b_hh0, b_ih1, b_hh1,
                                        W_out, b_out, (float*)d_out);
}